// round 14
// baseline (speedup 1.0000x reference)
#include <cuda_runtime.h>
#include <cuda_bf16.h>
#include <cstdint>
#include <cstddef>

// TMPNN: 7 steps of x += poly(x) @ W, M=131072, N=32, symmetric-folded basis.
// R14: M=32 rows/warp (B-fragment reuse of R13) + rolling-window register diet:
// y[4][12] (48 regs) -> base[4][4] + win[4][4] (32 regs), exploiting the
// d-ordered slot schedule (tile T<36: d=T>>2, a=T&3; slot reads y[a], y[a+d]).
// Window advances by one LDS.32 per slice per d-group. Budget spent on warps:
// CTA=128 threads, __launch_bounds__(128,5) -> 20 warps/SM (vs R13's 16).
// B table identical to R11/R13 (shift-orbit covering design, K=624, dups W=0).

namespace {

constexpr int N_STEPS = 7;
constexpr int NKT   = 39;            // k-tiles of 16 (K_mma = 624)
constexpr int XBSTR = 20;            // xsb row stride (uint32 bf16x2), 80 B
constexpr int ROWS  = 128;           // rows per CTA (32 per warp, 4 warps)

constexpr int SMEM_BYTES = ROWS * XBSTR * 4;    // 10240

__device__ __forceinline__ uint32_t pack2(float lo, float hi) {
    uint32_t r;
    asm("cvt.rn.bf16x2.f32 %0, %1, %2;" : "=r"(r) : "f"(hi), "f"(lo));
    return r;
}

__device__ __forceinline__ void mma16816(float* c, uint32_t a0, uint32_t a1,
                                         uint32_t a2, uint32_t a3,
                                         uint32_t b0, uint32_t b1) {
    asm volatile("mma.sync.aligned.m16n8k16.row.col.f32.bf16.bf16.f32 "
                 "{%0,%1,%2,%3}, {%4,%5,%6,%7}, {%8,%9}, {%0,%1,%2,%3};"
                 : "+f"(c[0]), "+f"(c[1]), "+f"(c[2]), "+f"(c[3])
                 : "r"(a0), "r"(a1), "r"(a2), "r"(a3), "r"(b0), "r"(b1));
}

// quad A-frag: u = broadcast half (hi? upper : lower) of b; v = w. One HMUL2.
__device__ __forceinline__ uint32_t qfrag(uint32_t b, uint32_t v, int hi) {
    const uint32_t u = __byte_perm(b, b, hi ? 0x3232 : 0x1010);
    uint32_t r;
    asm("mul.rn.bf16x2 %0, %1, %2;" : "=r"(r) : "r"(u), "r"(v));
    return r;
}

// ---- runtime W for B-table init (identical to R11/R13; dups get 0) ----
__device__ float wsym(const float* __restrict__ W, int i, int m, int n) {
    if (i == m) return __ldg(&W[(33 + i * 32 + i) * 32 + n]);
    return __ldg(&W[(33 + i * 32 + m) * 32 + n]) + __ldg(&W[(33 + m * 32 + i) * 32 + n]);
}

__device__ float wcell(const float* __restrict__ W, int S, int c, int j, int n) {
    if (S >= 77) return 0.0f;
    if (S == 76) return (j == 0 && c == 0) ? __ldg(&W[n]) : 0.0f;
    if (S >= 72) {
        const int pv = ((S - 72) + 4 * c) & 15;
        return __ldg(&W[(1 + 2 * pv + j) * 32 + n]);
    }
    const int d = S >> 3, a = (S >> 1) & 3, h = S & 1;
    const int A = (a + 4 * c) & 15;
    if (d == 0) {
        if (h == 1 && j == 0) return 0.0f;           // dup {2A+1, 2A}
        return wsym(W, 2 * A + h, 2 * A + j, n);
    }
    if (d == 8 && A >= 8) return 0.0f;               // reversed copy of {A-8, A}
    const int B = (A + d) & 15;
    return wsym(W, 2 * A + h, 2 * B + j, n);
}

} // namespace

// B-fragment tables: [0, NKT*32) = Lo (n 0..15), [NKT*32, 2*NKT*32) = Hi.
__device__ uint4 g_Bf[2 * NKT * 32];

__global__ void bf_init_kernel(const float* __restrict__ W) {
    const int idx = blockIdx.x * blockDim.x + threadIdx.x;
    if (idx >= 2 * NKT * 32) return;
    const int t   = idx / (NKT * 32);
    const int rem = idx - t * (NKT * 32);
    const int kt  = rem >> 5;
    const int l   = rem & 31;
    const int c   = l & 3;
    const int n0  = (l >> 2) + t * 16;
    uint4 q;
    q.x = pack2(wcell(W, 2 * kt,     c, 0, n0),     wcell(W, 2 * kt,     c, 1, n0));
    q.y = pack2(wcell(W, 2 * kt + 1, c, 0, n0),     wcell(W, 2 * kt + 1, c, 1, n0));
    q.z = pack2(wcell(W, 2 * kt,     c, 0, n0 + 8), wcell(W, 2 * kt,     c, 1, n0 + 8));
    q.w = pack2(wcell(W, 2 * kt + 1, c, 0, n0 + 8), wcell(W, 2 * kt + 1, c, 1, n0 + 8));
    g_Bf[idx] = q;
}

__global__ void __launch_bounds__(128, 5)
tmpnn_kernel(const float* __restrict__ X, float* __restrict__ out)
{
    extern __shared__ char smem[];
    uint32_t* xsb = reinterpret_cast<uint32_t*>(smem);   // [128][20] bf16x2

    const int tid  = threadIdx.x;
    const int lane = tid & 31;
    const int w    = tid >> 5;
    const int c    = lane & 3;               // fragment column group / data rotation
    const int r0   = w * 32 + (lane >> 2);   // rows r0, r0+8 (grp0); +16, +24 (grp1)
    const int cb   = c * 2;                  // accumulator col base

    // ---- stage bf16x2 X copy ----
    const float* Xb = X + (size_t)blockIdx.x * (ROWS * 32);
    for (int i = tid; i < ROWS * 16; i += 128) {
        const int rr = i >> 4, j = i & 15;
        const float2 v = __ldg(reinterpret_cast<const float2*>(Xb + rr * 32 + 2 * j));
        xsb[rr * XBSTR + j] = pack2(v.x, v.y);
    }

    // ---- fp32 residual in mma-accumulator layout (2 row groups) ----
    float res[2][4][4];
    #pragma unroll
    for (int g = 0; g < 2; ++g)
        #pragma unroll
        for (int nt = 0; nt < 4; ++nt) {
            const int cc = nt * 8 + cb;
            const int rg = r0 + 16 * g;
            const float2 v0 = __ldg(reinterpret_cast<const float2*>(Xb + rg * 32 + cc));
            const float2 v1 = __ldg(reinterpret_cast<const float2*>(Xb + (rg + 8) * 32 + cc));
            res[g][nt][0] = v0.x; res[g][nt][1] = v0.y;
            res[g][nt][2] = v1.x; res[g][nt][3] = v1.y;
        }
    __syncthreads();   // xsb visible (only CTA-wide barrier)

    const uint4* BfL = g_Bf + lane;
    const uint4* BfH = g_Bf + (NKT * 32) + lane;

    for (int step = 0; step < N_STEPS; ++step) {
        const bool full = (step != N_STEPS - 1);   // last step: only n 0..7 needed

        // base[s][i] = xpair[row_s][(i+4c)&15], i=0..3  (one LDS.128 per slice)
        // win = rolling window y[d..d+3]; starts equal to base (d=0).
        uint32_t base[4][4], win[4][4];
        #pragma unroll
        for (int s = 0; s < 4; ++s) {
            const int rr = r0 + 8 * s;
            const uint4 t4 = *reinterpret_cast<const uint4*>(&xsb[rr * XBSTR + 4 * c]);
            base[s][0] = t4.x; base[s][1] = t4.y; base[s][2] = t4.z; base[s][3] = t4.w;
            win[s][0]  = t4.x; win[s][1]  = t4.y; win[s][2]  = t4.z; win[s][3]  = t4.w;
        }

#define MMAS(T, A00, A01, A02, A03, A10, A11, A12, A13) {                  \
            const uint4 ql = __ldg(BfL + (T) * 32);                        \
            mma16816(res[0][0], A00, A01, A02, A03, ql.x, ql.y);           \
            mma16816(res[1][0], A10, A11, A12, A13, ql.x, ql.y);           \
            if (full) {                                                    \
                mma16816(res[0][1], A00, A01, A02, A03, ql.z, ql.w);       \
                mma16816(res[1][1], A10, A11, A12, A13, ql.z, ql.w);       \
                const uint4 qh = __ldg(BfH + (T) * 32);                    \
                mma16816(res[0][2], A00, A01, A02, A03, qh.x, qh.y);       \
                mma16816(res[1][2], A10, A11, A12, A13, qh.x, qh.y);       \
                mma16816(res[0][3], A00, A01, A02, A03, qh.z, qh.w);       \
                mma16816(res[1][3], A10, A11, A12, A13, qh.z, qh.w);       \
            }                                                              \
        }

        // quad tile T (<36): a = T&3; u from base[s][a] (h = slot parity),
        // v = win[s][a] (= y[a + d]).
#define QTILE(T) {                                                         \
            const int a_ = (T) & 3;                                        \
            const uint32_t a00 = qfrag(base[0][a_], win[0][a_], 0);        \
            const uint32_t a01 = qfrag(base[1][a_], win[1][a_], 0);        \
            const uint32_t a02 = qfrag(base[0][a_], win[0][a_], 1);        \
            const uint32_t a03 = qfrag(base[1][a_], win[1][a_], 1);        \
            const uint32_t a10 = qfrag(base[2][a_], win[2][a_], 0);        \
            const uint32_t a11 = qfrag(base[3][a_], win[3][a_], 0);        \
            const uint32_t a12 = qfrag(base[2][a_], win[2][a_], 1);        \
            const uint32_t a13 = qfrag(base[3][a_], win[3][a_], 1);        \
            MMAS(T, a00, a01, a02, a03, a10, a11, a12, a13)                \
        }

        // advance window to d = G: win[i] <- y[G + i]
#define WSHIFT(G) {                                                        \
            _Pragma("unroll")                                              \
            for (int s = 0; s < 4; ++s) {                                  \
                win[s][0] = win[s][1];                                     \
                win[s][1] = win[s][2];                                     \
                win[s][2] = win[s][3];                                     \
                const int rr = r0 + 8 * s;                                 \
                win[s][3] = xsb[rr * XBSTR + (((G) + 3 + 4 * c) & 15)];    \
            }                                                              \
        }

        // linear tile: frags are natural pairs base[s][i0], base[s][i1]
#define LTILE(T, I0, I1) {                                                 \
            const uint32_t a00 = base[0][I0], a01 = base[1][I0];           \
            const uint32_t a02 = base[0][I1], a03 = base[1][I1];           \
            const uint32_t a10 = base[2][I0], a11 = base[3][I0];           \
            const uint32_t a12 = base[2][I1], a13 = base[3][I1];           \
            MMAS(T, a00, a01, a02, a03, a10, a11, a12, a13)                \
        }

        QTILE(0)  QTILE(1)  QTILE(2)  QTILE(3)   WSHIFT(1)
        QTILE(4)  QTILE(5)  QTILE(6)  QTILE(7)   WSHIFT(2)
        QTILE(8)  QTILE(9)  QTILE(10) QTILE(11)  WSHIFT(3)
        QTILE(12) QTILE(13) QTILE(14) QTILE(15)  WSHIFT(4)
        QTILE(16) QTILE(17) QTILE(18) QTILE(19)  WSHIFT(5)
        QTILE(20) QTILE(21) QTILE(22) QTILE(23)  WSHIFT(6)
        QTILE(24) QTILE(25) QTILE(26) QTILE(27)  WSHIFT(7)
        QTILE(28) QTILE(29) QTILE(30) QTILE(31)  WSHIFT(8)
        QTILE(32) QTILE(33) QTILE(34) QTILE(35)
        LTILE(36, 0, 1)
        LTILE(37, 2, 3)
        {   // tile 38: slot 76 = {bias=1, 0}; slot 77 = zero pad
            const uint32_t ab = 0x00003F80u, az = 0u;
            MMAS(38, ab, ab, az, az, ab, ab, az, az)
        }
#undef LTILE
#undef WSHIFT
#undef QTILE
#undef MMAS

        // ---- epilogue: refresh bf16x2 copy from accumulator registers ----
        if (full) {
            __syncwarp();   // reads of this step done before xsb overwrite
            #pragma unroll
            for (int g = 0; g < 2; ++g)
                #pragma unroll
                for (int nt = 0; nt < 4; ++nt) {
                    const int cc = nt * 8 + cb;
                    const int rg = r0 + 16 * g;
                    xsb[rg * XBSTR + (cc >> 1)]       = pack2(res[g][nt][0], res[g][nt][1]);
                    xsb[(rg + 8) * XBSTR + (cc >> 1)] = pack2(res[g][nt][2], res[g][nt][3]);
                }
            __syncwarp();   // visible to next step's base/window reload
        }
    }

    if (c == 0) {
        const size_t obase = (size_t)blockIdx.x * ROWS;
        out[obase + r0]      = res[0][0][0];
        out[obase + r0 + 8]  = res[0][0][2];
        out[obase + r0 + 16] = res[1][0][0];
        out[obase + r0 + 24] = res[1][0][2];
    }
}

extern "C" void kernel_launch(void* const* d_in, const int* in_sizes, int n_in,
                              void* d_out, int out_size) {
    const float* X = (const float*)d_in[0];
    const float* W = (const float*)d_in[1];
    float* out = (float*)d_out;
    const int rows = in_sizes[0] / 32;
    const int blocks = rows / ROWS;
    bf_init_kernel<<<(2 * NKT * 32 + 255) / 256, 256>>>(W);
    cudaFuncSetAttribute(tmpnn_kernel, cudaFuncAttributeMaxDynamicSharedMemorySize,
                         SMEM_BYTES);
    tmpnn_kernel<<<blocks, 128, SMEM_BYTES>>>(X, out);
}